// round 10
// baseline (speedup 1.0000x reference)
#include <cuda_runtime.h>
#include <cuda_fp16.h>
#include <cuda_bf16.h>

#define N_NODES_MAX 100000
#define HIDDEN 64
#define STRIDE_H 72    // weight smem stride (halves)
#define CST_STRIDE 68  // C-stage stride (half2 units) -> conflict-free STS

// Per-node fp16 projections with |W2| and 0.5*b1 folded in:
//   u''_k = (z @ W1[0:64,:])_k   * |w2_k| + 0.5*b1_k*|w2_k|
//   v''_k = (z @ W1[64:128,:])_k * |w2_k| + 0.5*b1_k*|w2_k|
// Edge: out = sum_k sign(w2_k) * relu(u''_k + v''_k) + b2
__device__ uint4  g_u[N_NODES_MAX * 8];
__device__ uint4  g_v[N_NODES_MAX * 8];
__device__ uint4  g_whh4[1024];       // packed [128][64] fp16 hi weights
__device__ uint4  g_whl4[1024];       // packed [128][64] fp16 lo weights
__device__ float  g_b1c[128];         // folded bias
__device__ int    g_idx_is64;

#define MMA16816(c0, c1, c2, c3, a0, a1, a2, a3, b0, b1)                  \
    asm volatile(                                                          \
        "mma.sync.aligned.m16n8k16.row.col.f32.f16.f16.f32 "              \
        "{%0,%1,%2,%3}, {%4,%5,%6,%7}, {%8,%9}, {%0,%1,%2,%3};"           \
        : "+f"(c0), "+f"(c1), "+f"(c2), "+f"(c3)                           \
        : "r"(a0), "r"(a1), "r"(a2), "r"(a3), "r"(b0), "r"(b1))

__device__ __forceinline__ unsigned h2_as_u32(__half2 h) {
    return *(unsigned*)&h;
}

// ---------------------------------------------------------------------------
// Prepare kernel (1 block, 256 threads): split-precision |w2|-scaled
// transposed weights into packed gmem scratch, folded bias, dtype detect.
// ---------------------------------------------------------------------------
__global__ void prepare_kernel(const float* __restrict__ W1,
                               const float* __restrict__ b1,
                               const float* __restrict__ W2,
                               const int* __restrict__ ei_as_i32) {
    __shared__ int s_nz[4];
    const int tid = threadIdx.x;

    if (tid < 128) {
        int nz = (ei_as_i32[2 * tid + 1] != 0) ? 1 : 0;
        unsigned b = __ballot_sync(0xffffffffu, nz);
        if ((tid & 31) == 0) s_nz[tid >> 5] = (b != 0);
    }

    __half* whh = (__half*)g_whh4;
    __half* whl = (__half*)g_whl4;
    // W1 linear i = j*64+m: j<64 -> (n=m, k=j) u-part; j>=64 -> (n=64+m, k=j-64)
    for (int i = tid; i < 128 * HIDDEN; i += 256) {
        const int j = i >> 6, m = i & 63;
        const int n = (j < HIDDEN) ? m : (HIDDEN + m);
        const int k = (j < HIDDEN) ? j : (j - HIDDEN);
        const float w = W1[i] * fabsf(W2[m]);
        const __half hi = __float2half_rn(w);
        const __half lo = __float2half_rn(w - __half2float(hi));
        whh[n * HIDDEN + k] = hi;
        whl[n * HIDDEN + k] = lo;
    }
    if (tid < 128) {
        const int m = tid & (HIDDEN - 1);
        g_b1c[tid] = 0.5f * b1[m] * fabsf(W2[m]);
    }
    __syncthreads();
    if (tid == 0)
        g_idx_is64 = !(s_nz[0] | s_nz[1] | s_nz[2] | s_nz[3]);
}

// ---------------------------------------------------------------------------
// Precompute via tensor cores (split-precision fp16 mma, fp32 accum):
//   acc = zh@wh + zh@wl + zl@wh   (dropped zl@wl ~ 2^-22 relative)
// Block = 256 threads (8 warps) = 128 nodes; warp = 16 nodes.
// Weights staged from prepared gmem scratch via plain 16B copies.
// Epilogue stages C in smem then stores fully coalesced 512B runs.
// ---------------------------------------------------------------------------
__global__ __launch_bounds__(256)
void precompute_uv_kernel(const float* __restrict__ z, int n_nodes) {
    extern __shared__ __align__(16) char smem_raw[];
    __half*  whh = (__half*)smem_raw;                    // [128][STRIDE_H]
    __half*  whl = whh + 128 * STRIDE_H;                 // [128][STRIDE_H]
    float*   b1c = (float*)(whl + 128 * STRIDE_H);       // [128]
    __half2* cst = (__half2*)(b1c + 128);                // 8 warps x 16 x CST_STRIDE

    const int tid = threadIdx.x;

    // Stage weights: 1024 uint4 per array; smem row base n*STRIDE_H*2 bytes
    // (144B) is 16B-aligned, chunk offset k0*2 likewise.
    #pragma unroll
    for (int q = 0; q < 4; q++) {
        const int i4 = q * 256 + tid;
        const int n = i4 >> 3, ch = i4 & 7;
        *(uint4*)&whh[n * STRIDE_H + ch * 8] = g_whh4[i4];
        *(uint4*)&whl[n * STRIDE_H + ch * 8] = g_whl4[i4];
    }
    if (tid < 128) b1c[tid] = g_b1c[tid];
    __syncthreads();

    const int warp = tid >> 5, lane = tid & 31;
    const int g = lane >> 2, tig = lane & 3;
    const long long wbase = (long long)blockIdx.x * 128 + warp * 16;
    if (wbase >= n_nodes) return;

    float acc[16][4];
    #pragma unroll
    for (int t = 0; t < 16; t++) {
        const int c = t * 8 + tig * 2;
        acc[t][0] = b1c[c];  acc[t][1] = b1c[c + 1];
        acc[t][2] = b1c[c];  acc[t][3] = b1c[c + 1];
    }

    const long long r0 = (wbase + g     < n_nodes) ? (wbase + g)     : (n_nodes - 1);
    const long long r1 = (wbase + g + 8 < n_nodes) ? (wbase + g + 8) : (n_nodes - 1);

    #pragma unroll
    for (int kt = 0; kt < 4; kt++) {
        const int k0 = kt * 16;
        const float2 f0 = *(const float2*)&z[r0 * HIDDEN + k0 + tig * 2];
        const float2 f1 = *(const float2*)&z[r1 * HIDDEN + k0 + tig * 2];
        const float2 f2 = *(const float2*)&z[r0 * HIDDEN + k0 + 8 + tig * 2];
        const float2 f3 = *(const float2*)&z[r1 * HIDDEN + k0 + 8 + tig * 2];

        __half2 h; float2 hf;
        unsigned ah[4], al[4];
        h = __floats2half2_rn(f0.x, f0.y); ah[0] = h2_as_u32(h);
        hf = __half22float2(h);
        al[0] = h2_as_u32(__floats2half2_rn(f0.x - hf.x, f0.y - hf.y));
        h = __floats2half2_rn(f1.x, f1.y); ah[1] = h2_as_u32(h);
        hf = __half22float2(h);
        al[1] = h2_as_u32(__floats2half2_rn(f1.x - hf.x, f1.y - hf.y));
        h = __floats2half2_rn(f2.x, f2.y); ah[2] = h2_as_u32(h);
        hf = __half22float2(h);
        al[2] = h2_as_u32(__floats2half2_rn(f2.x - hf.x, f2.y - hf.y));
        h = __floats2half2_rn(f3.x, f3.y); ah[3] = h2_as_u32(h);
        hf = __half22float2(h);
        al[3] = h2_as_u32(__floats2half2_rn(f3.x - hf.x, f3.y - hf.y));

        #pragma unroll
        for (int t = 0; t < 16; t++) {
            const int nb = t * 8 + g;
            const unsigned bh0 = *(const unsigned*)&whh[nb * STRIDE_H + k0 + tig * 2];
            const unsigned bh1 = *(const unsigned*)&whh[nb * STRIDE_H + k0 + 8 + tig * 2];
            const unsigned bl0 = *(const unsigned*)&whl[nb * STRIDE_H + k0 + tig * 2];
            const unsigned bl1 = *(const unsigned*)&whl[nb * STRIDE_H + k0 + 8 + tig * 2];
            MMA16816(acc[t][0], acc[t][1], acc[t][2], acc[t][3],
                     ah[0], ah[1], ah[2], ah[3], bh0, bh1);
            MMA16816(acc[t][0], acc[t][1], acc[t][2], acc[t][3],
                     ah[0], ah[1], ah[2], ah[3], bl0, bl1);
            MMA16816(acc[t][0], acc[t][1], acc[t][2], acc[t][3],
                     al[0], al[1], al[2], al[3], bh0, bh1);
        }
    }

    // Epilogue: stage C in smem (conflict-free), then coalesced 512B stores.
    __half2* cw = cst + warp * 16 * CST_STRIDE;
    #pragma unroll
    for (int t = 0; t < 16; t++) {
        cw[g * CST_STRIDE + t * 4 + tig]       = __floats2half2_rn(acc[t][0], acc[t][1]);
        cw[(g + 8) * CST_STRIDE + t * 4 + tig] = __floats2half2_rn(acc[t][2], acc[t][3]);
    }
    __syncwarp();

    #pragma unroll
    for (int q = 0; q < 4; q++) {
        const int nl = q * 4 + (lane >> 3);     // local node 0..15
        const int ch = lane & 7;                // uint4 chunk 0..7
        const long long gn = wbase + nl;
        if (gn < n_nodes) {
            g_u[gn * 8 + ch] = *(const uint4*)&cw[nl * CST_STRIDE + ch * 4];
            g_v[gn * 8 + ch] = *(const uint4*)&cw[nl * CST_STRIDE + 32 + ch * 4];
        }
    }
}

// ---------------------------------------------------------------------------
// One lane's 8-column signed-relu partial (b1,|W2| folded; sign = exact +-1).
// ---------------------------------------------------------------------------
__device__ __forceinline__ float oct_partial(uint4 u, uint4 v,
                                             const __half2* __restrict__ sg) {
    const __half2* up = (const __half2*)&u;
    const __half2* vp = (const __half2*)&v;
    const __half2 z2 = __float2half2_rn(0.f);
    __half2 acc2 = __hmul2(__hmax2(__hadd2(up[0], vp[0]), z2), sg[0]);
    acc2 = __hfma2(__hmax2(__hadd2(up[1], vp[1]), z2), sg[1], acc2);
    acc2 = __hfma2(__hmax2(__hadd2(up[2], vp[2]), z2), sg[2], acc2);
    acc2 = __hfma2(__hmax2(__hadd2(up[3], vp[3]), z2), sg[3], acc2);
    const float2 f = __half22float2(acc2);
    return f.x + f.y;
}

// ---------------------------------------------------------------------------
// Edge kernel: 32 edges/warp; coalesced index load; 8 unrolled substeps of
// 4 edges; 8 lanes/edge gather one 16B chunk of u''[row], v''[col] via
// __ldcg (L2-resident data: skip L1 allocation/fill).
// ---------------------------------------------------------------------------
template <bool FULL>
__device__ __forceinline__
void edge_tile(const long long base, int r_all, int c_all,
               const __half2* sg, float bias2, float* __restrict__ out,
               int n_edges, int oct, int j) {
    #pragma unroll
    for (int s = 0; s < 8; s++) {
        const int e_off = s * 4 + oct;
        const int r = __shfl_sync(0xffffffffu, r_all, e_off);
        const int c = __shfl_sync(0xffffffffu, c_all, e_off);

        const uint4 u = __ldcg(&g_u[(size_t)r * 8 + j]);
        const uint4 v = __ldcg(&g_v[(size_t)c * 8 + j]);

        float acc = oct_partial(u, v, sg);
        acc += __shfl_xor_sync(0xffffffffu, acc, 1);
        acc += __shfl_xor_sync(0xffffffffu, acc, 2);
        acc += __shfl_xor_sync(0xffffffffu, acc, 4);

        if (j == 0) {
            const long long e = base + e_off;
            if (FULL || e < n_edges) out[e] = acc + bias2;
        }
    }
}

__global__ __launch_bounds__(256)
void edge_decode_kernel(const void* __restrict__ ei_raw,
                        const float* __restrict__ W2,
                        const float* __restrict__ b2,
                        float* __restrict__ out,
                        int n_edges) {
    const int lane = threadIdx.x & 31;
    const int oct  = lane >> 3;
    const int j    = lane & 7;

    const long long base =
        (long long)((blockIdx.x * blockDim.x + threadIdx.x) >> 5) * 32;
    if (base >= n_edges) return;

    const int is64 = g_idx_is64;
    const long long* __restrict__ ei64 = (const long long*)ei_raw;
    const int*       __restrict__ ei32 = (const int*)ei_raw;

    const long long eL = base + lane;
    const bool haveL = eL < n_edges;
    int r_all, c_all;
    if (is64) {
        r_all = haveL ? (int)ei64[eL] : 0;
        c_all = haveL ? (int)ei64[(long long)n_edges + eL] : 0;
    } else {
        r_all = haveL ? ei32[eL] : 0;
        c_all = haveL ? ei32[(long long)n_edges + eL] : 0;
    }

    __half2 sg[4];
    #pragma unroll
    for (int i = 0; i < 4; i++)
        sg[i] = __floats2half2_rn(copysignf(1.f, W2[8 * j + 2 * i]),
                                  copysignf(1.f, W2[8 * j + 2 * i + 1]));
    const float bias2 = b2[0];

    if (base + 32 <= (long long)n_edges)
        edge_tile<true >(base, r_all, c_all, sg, bias2, out, n_edges, oct, j);
    else
        edge_tile<false>(base, r_all, c_all, sg, bias2, out, n_edges, oct, j);
}

// ---------------------------------------------------------------------------
// Launch. Inputs: z, edge_index [2,E], W1, b1, W2, b2. Output: f32 [E,1].
// ---------------------------------------------------------------------------
extern "C" void kernel_launch(void* const* d_in, const int* in_sizes, int n_in,
                              void* d_out, int out_size) {
    const float* z  = (const float*)d_in[0];
    const void*  ei = d_in[1];
    const float* W1 = (const float*)d_in[2];
    const float* b1 = (const float*)d_in[3];
    const float* W2 = (const float*)d_in[4];
    const float* b2 = (const float*)d_in[5];
    float* out = (float*)d_out;

    const int n_nodes = in_sizes[0] / HIDDEN;
    const int n_edges = in_sizes[1] / 2;

    // Phase 0: weight split + bias fold + dtype detect (1 block).
    prepare_kernel<<<1, 256>>>(W1, b1, W2, (const int*)ei);

    // Phase 1: tensor-core projections.
    {
        const int smem_bytes = 2 * 128 * STRIDE_H * 2      // whh + whl
                             + 128 * 4                     // b1c
                             + 8 * 16 * CST_STRIDE * 4;    // C stage
        cudaFuncSetAttribute(precompute_uv_kernel,
                             cudaFuncAttributeMaxDynamicSharedMemorySize,
                             smem_bytes);
        const int blocks = (n_nodes + 127) / 128;
        precompute_uv_kernel<<<blocks, 256, smem_bytes>>>(z, n_nodes);
    }

    // Phase 2: edge decode (L1-bypassed gathers).
    {
        const int threads = 256;
        const int edges_per_block = 256;   // 8 warps x 32 edges
        const int blocks = (n_edges + edges_per_block - 1) / edges_per_block;
        edge_decode_kernel<<<blocks, threads>>>(ei, W2, b2, out, n_edges);
    }
}

// round 11
// speedup vs baseline: 1.2445x; 1.2445x over previous
#include <cuda_runtime.h>
#include <cuda_fp16.h>
#include <cuda_bf16.h>

#define N_NODES_MAX 100000
#define HIDDEN 64
#define STRIDE_H 72    // weight smem stride (halves)
#define CST_STRIDE 68  // C-stage stride (half2 units) -> conflict-free STS

// Per-node fp16 projections with |W2| and 0.5*b1 folded in:
//   u''_k = (z @ W1[0:64,:])_k   * |w2_k| + 0.5*b1_k*|w2_k|
//   v''_k = (z @ W1[64:128,:])_k * |w2_k| + 0.5*b1_k*|w2_k|
// Edge: out = sum_k sign(w2_k) * relu(u''_k + v''_k) + b2
__device__ uint4 g_u[N_NODES_MAX * 8];
__device__ uint4 g_v[N_NODES_MAX * 8];
__device__ int   g_idx_is64;

#define MMA16816(c0, c1, c2, c3, a0, a1, a2, a3, b0, b1)                  \
    asm volatile(                                                          \
        "mma.sync.aligned.m16n8k16.row.col.f32.f16.f16.f32 "              \
        "{%0,%1,%2,%3}, {%4,%5,%6,%7}, {%8,%9}, {%0,%1,%2,%3};"           \
        : "+f"(c0), "+f"(c1), "+f"(c2), "+f"(c3)                           \
        : "r"(a0), "r"(a1), "r"(a2), "r"(a3), "r"(b0), "r"(b1))

__device__ __forceinline__ unsigned h2_as_u32(__half2 h) {
    return *(unsigned*)&h;
}

// ---------------------------------------------------------------------------
// Precompute via tensor cores (split-precision fp16 mma, fp32 accum):
//   acc = zh@wh + zh@wl + zl@wh   (dropped zl@wl ~ 2^-22 relative)
// PERSISTENT grid: each block preps weights in smem ONCE, then grid-strides
// over 128-node tiles (amortizes the prep over ~2.6 tiles).
// Epilogue stages C in smem then stores fully coalesced 512B runs.
// ---------------------------------------------------------------------------
__global__ __launch_bounds__(256)
void precompute_uv_kernel(const float* __restrict__ z,
                          const float* __restrict__ W1,
                          const float* __restrict__ b1,
                          const float* __restrict__ W2,
                          const int* __restrict__ ei_as_i32,
                          int n_nodes, int n_tiles) {
    extern __shared__ __align__(16) char smem_raw[];
    __half*  whh = (__half*)smem_raw;                    // [128][STRIDE_H]
    __half*  whl = whh + 128 * STRIDE_H;                 // [128][STRIDE_H]
    float*   b1c = (float*)(whl + 128 * STRIDE_H);       // [128]
    __half2* cst = (__half2*)(b1c + 128);                // 8 warps x 16 x CST_STRIDE

    __shared__ int s_nz[4];
    const int tid = threadIdx.x;

    // dtype detection (block 0, warps 0-3 fully active)
    if (blockIdx.x == 0 && tid < 128) {
        int nz = (ei_as_i32[2 * tid + 1] != 0) ? 1 : 0;
        unsigned b = __ballot_sync(0xffffffffu, nz);
        if ((tid & 31) == 0) s_nz[tid >> 5] = (b != 0);
    }

    // Stage split-precision, |w2|-scaled, transposed weights (once per block).
    // W1 linear i = j*64+m: j<64 -> (n=m, k=j) u-part; j>=64 -> (n=64+m, k=j-64).
    for (int i = tid; i < 128 * HIDDEN; i += 256) {
        const int j = i >> 6, m = i & 63;
        const int n = (j < HIDDEN) ? m : (HIDDEN + m);
        const int k = (j < HIDDEN) ? j : (j - HIDDEN);
        const float w = W1[i] * fabsf(W2[m]);
        const __half hi = __float2half_rn(w);
        const __half lo = __float2half_rn(w - __half2float(hi));
        whh[n * STRIDE_H + k] = hi;
        whl[n * STRIDE_H + k] = lo;
    }
    if (tid < 128) {
        const int m = tid & (HIDDEN - 1);
        b1c[tid] = 0.5f * b1[m] * fabsf(W2[m]);
    }
    __syncthreads();

    if (blockIdx.x == 0 && tid == 0)
        g_idx_is64 = !(s_nz[0] | s_nz[1] | s_nz[2] | s_nz[3]);

    const int warp = tid >> 5, lane = tid & 31;
    const int g = lane >> 2, tig = lane & 3;

    for (int tile = blockIdx.x; tile < n_tiles; tile += gridDim.x) {
        const long long wbase = (long long)tile * 128 + warp * 16;
        if (wbase >= n_nodes) continue;

        float acc[16][4];
        #pragma unroll
        for (int t = 0; t < 16; t++) {
            const int c = t * 8 + tig * 2;
            acc[t][0] = b1c[c];  acc[t][1] = b1c[c + 1];
            acc[t][2] = b1c[c];  acc[t][3] = b1c[c + 1];
        }

        const long long r0 = (wbase + g     < n_nodes) ? (wbase + g)     : (n_nodes - 1);
        const long long r1 = (wbase + g + 8 < n_nodes) ? (wbase + g + 8) : (n_nodes - 1);

        #pragma unroll
        for (int kt = 0; kt < 4; kt++) {
            const int k0 = kt * 16;
            const float2 f0 = *(const float2*)&z[r0 * HIDDEN + k0 + tig * 2];
            const float2 f1 = *(const float2*)&z[r1 * HIDDEN + k0 + tig * 2];
            const float2 f2 = *(const float2*)&z[r0 * HIDDEN + k0 + 8 + tig * 2];
            const float2 f3 = *(const float2*)&z[r1 * HIDDEN + k0 + 8 + tig * 2];

            __half2 h; float2 hf;
            unsigned ah[4], al[4];
            h = __floats2half2_rn(f0.x, f0.y); ah[0] = h2_as_u32(h);
            hf = __half22float2(h);
            al[0] = h2_as_u32(__floats2half2_rn(f0.x - hf.x, f0.y - hf.y));
            h = __floats2half2_rn(f1.x, f1.y); ah[1] = h2_as_u32(h);
            hf = __half22float2(h);
            al[1] = h2_as_u32(__floats2half2_rn(f1.x - hf.x, f1.y - hf.y));
            h = __floats2half2_rn(f2.x, f2.y); ah[2] = h2_as_u32(h);
            hf = __half22float2(h);
            al[2] = h2_as_u32(__floats2half2_rn(f2.x - hf.x, f2.y - hf.y));
            h = __floats2half2_rn(f3.x, f3.y); ah[3] = h2_as_u32(h);
            hf = __half22float2(h);
            al[3] = h2_as_u32(__floats2half2_rn(f3.x - hf.x, f3.y - hf.y));

            #pragma unroll
            for (int t = 0; t < 16; t++) {
                const int nb = t * 8 + g;
                const unsigned bh0 = *(const unsigned*)&whh[nb * STRIDE_H + k0 + tig * 2];
                const unsigned bh1 = *(const unsigned*)&whh[nb * STRIDE_H + k0 + 8 + tig * 2];
                const unsigned bl0 = *(const unsigned*)&whl[nb * STRIDE_H + k0 + tig * 2];
                const unsigned bl1 = *(const unsigned*)&whl[nb * STRIDE_H + k0 + 8 + tig * 2];
                MMA16816(acc[t][0], acc[t][1], acc[t][2], acc[t][3],
                         ah[0], ah[1], ah[2], ah[3], bh0, bh1);
                MMA16816(acc[t][0], acc[t][1], acc[t][2], acc[t][3],
                         ah[0], ah[1], ah[2], ah[3], bl0, bl1);
                MMA16816(acc[t][0], acc[t][1], acc[t][2], acc[t][3],
                         al[0], al[1], al[2], al[3], bh0, bh1);
            }
        }

        // Epilogue: stage C in smem (conflict-free), then coalesced stores.
        __half2* cw = cst + warp * 16 * CST_STRIDE;
        #pragma unroll
        for (int t = 0; t < 16; t++) {
            cw[g * CST_STRIDE + t * 4 + tig]       = __floats2half2_rn(acc[t][0], acc[t][1]);
            cw[(g + 8) * CST_STRIDE + t * 4 + tig] = __floats2half2_rn(acc[t][2], acc[t][3]);
        }
        __syncwarp();

        #pragma unroll
        for (int q = 0; q < 4; q++) {
            const int nl = q * 4 + (lane >> 3);     // local node 0..15
            const int ch = lane & 7;                // uint4 chunk 0..7
            const long long gn = wbase + nl;
            if (gn < n_nodes) {
                g_u[gn * 8 + ch] = *(const uint4*)&cw[nl * CST_STRIDE + ch * 4];
                g_v[gn * 8 + ch] = *(const uint4*)&cw[nl * CST_STRIDE + 32 + ch * 4];
            }
        }
        __syncwarp();
    }
}

// ---------------------------------------------------------------------------
// One lane's 8-column signed-relu partial (b1,|W2| folded; sign = exact +-1).
// ---------------------------------------------------------------------------
__device__ __forceinline__ float oct_partial(uint4 u, uint4 v,
                                             const __half2* __restrict__ sg) {
    const __half2* up = (const __half2*)&u;
    const __half2* vp = (const __half2*)&v;
    const __half2 z2 = __float2half2_rn(0.f);
    __half2 acc2 = __hmul2(__hmax2(__hadd2(up[0], vp[0]), z2), sg[0]);
    acc2 = __hfma2(__hmax2(__hadd2(up[1], vp[1]), z2), sg[1], acc2);
    acc2 = __hfma2(__hmax2(__hadd2(up[2], vp[2]), z2), sg[2], acc2);
    acc2 = __hfma2(__hmax2(__hadd2(up[3], vp[3]), z2), sg[3], acc2);
    const float2 f = __half22float2(acc2);
    return f.x + f.y;
}

// ---------------------------------------------------------------------------
// Edge kernel: 32 edges/warp; coalesced index load; 8 unrolled substeps of
// 4 edges; 8 lanes/edge gather one 16B chunk of u''[row], v''[col] via
// __ldcg (L2-resident data: skip L1 allocation/fill). At the LTS cap.
// ---------------------------------------------------------------------------
template <bool FULL>
__device__ __forceinline__
void edge_tile(const long long base, int r_all, int c_all,
               const __half2* sg, float bias2, float* __restrict__ out,
               int n_edges, int oct, int j) {
    #pragma unroll
    for (int s = 0; s < 8; s++) {
        const int e_off = s * 4 + oct;
        const int r = __shfl_sync(0xffffffffu, r_all, e_off);
        const int c = __shfl_sync(0xffffffffu, c_all, e_off);

        const uint4 u = __ldcg(&g_u[(size_t)r * 8 + j]);
        const uint4 v = __ldcg(&g_v[(size_t)c * 8 + j]);

        float acc = oct_partial(u, v, sg);
        acc += __shfl_xor_sync(0xffffffffu, acc, 1);
        acc += __shfl_xor_sync(0xffffffffu, acc, 2);
        acc += __shfl_xor_sync(0xffffffffu, acc, 4);

        if (j == 0) {
            const long long e = base + e_off;
            if (FULL || e < n_edges) out[e] = acc + bias2;
        }
    }
}

__global__ __launch_bounds__(256)
void edge_decode_kernel(const void* __restrict__ ei_raw,
                        const float* __restrict__ W2,
                        const float* __restrict__ b2,
                        float* __restrict__ out,
                        int n_edges) {
    const int lane = threadIdx.x & 31;
    const int oct  = lane >> 3;
    const int j    = lane & 7;

    const long long base =
        (long long)((blockIdx.x * blockDim.x + threadIdx.x) >> 5) * 32;
    if (base >= n_edges) return;

    const int is64 = g_idx_is64;
    const long long* __restrict__ ei64 = (const long long*)ei_raw;
    const int*       __restrict__ ei32 = (const int*)ei_raw;

    const long long eL = base + lane;
    const bool haveL = eL < n_edges;
    int r_all, c_all;
    if (is64) {
        r_all = haveL ? (int)ei64[eL] : 0;
        c_all = haveL ? (int)ei64[(long long)n_edges + eL] : 0;
    } else {
        r_all = haveL ? ei32[eL] : 0;
        c_all = haveL ? ei32[(long long)n_edges + eL] : 0;
    }

    __half2 sg[4];
    #pragma unroll
    for (int i = 0; i < 4; i++)
        sg[i] = __floats2half2_rn(copysignf(1.f, W2[8 * j + 2 * i]),
                                  copysignf(1.f, W2[8 * j + 2 * i + 1]));
    const float bias2 = b2[0];

    if (base + 32 <= (long long)n_edges)
        edge_tile<true >(base, r_all, c_all, sg, bias2, out, n_edges, oct, j);
    else
        edge_tile<false>(base, r_all, c_all, sg, bias2, out, n_edges, oct, j);
}

// ---------------------------------------------------------------------------
// Launch. Inputs: z, edge_index [2,E], W1, b1, W2, b2. Output: f32 [E,1].
// ---------------------------------------------------------------------------
extern "C" void kernel_launch(void* const* d_in, const int* in_sizes, int n_in,
                              void* d_out, int out_size) {
    const float* z  = (const float*)d_in[0];
    const void*  ei = d_in[1];
    const float* W1 = (const float*)d_in[2];
    const float* b1 = (const float*)d_in[3];
    const float* W2 = (const float*)d_in[4];
    const float* b2 = (const float*)d_in[5];
    float* out = (float*)d_out;

    const int n_nodes = in_sizes[0] / HIDDEN;
    const int n_edges = in_sizes[1] / 2;

    // Phase 1: persistent tensor-core projections (prep amortized in-block).
    {
        const int smem_bytes = 2 * 128 * STRIDE_H * 2      // whh + whl
                             + 128 * 4                     // b1c
                             + 8 * 16 * CST_STRIDE * 4;    // C stage
        cudaFuncSetAttribute(precompute_uv_kernel,
                             cudaFuncAttributeMaxDynamicSharedMemorySize,
                             smem_bytes);
        const int n_tiles = (n_nodes + 127) / 128;
        int blocks = 296;                                  // 2 per SM
        if (blocks > n_tiles) blocks = n_tiles;
        precompute_uv_kernel<<<blocks, 256, smem_bytes>>>(
            z, W1, b1, W2, (const int*)ei, n_nodes, n_tiles);
    }

    // Phase 2: edge decode (L1-bypassed gathers, at LTS cap).
    {
        const int threads = 256;
        const int edges_per_block = 256;   // 8 warps x 32 edges
        const int blocks = (n_edges + edges_per_block - 1) / edges_per_block;
        edge_decode_kernel<<<blocks, threads>>>(ei, W2, b2, out, n_edges);
    }
}

// round 12
// speedup vs baseline: 1.3218x; 1.0621x over previous
#include <cuda_runtime.h>
#include <cuda_fp16.h>
#include <cuda_bf16.h>

#define N_NODES_MAX 100000
#define HIDDEN 64
#define STRIDE_H 72    // weight smem stride (halves): conflict-free B frags
#define ZST_STRIDE 72  // z-stage stride (floats): uniform 2-way LDS.64 conflicts
#define CST_STRIDE 68  // C-stage stride (half2 units): conflict-free STS

// Per-node fp16 projections with |W2| and 0.5*b1 folded in:
//   u''_k = (z @ W1[0:64,:])_k   * |w2_k| + 0.5*b1_k*|w2_k|
//   v''_k = (z @ W1[64:128,:])_k * |w2_k| + 0.5*b1_k*|w2_k|
// Edge: out = sum_k sign(w2_k) * relu(u''_k + v''_k) + b2
__device__ uint4 g_u[N_NODES_MAX * 8];
__device__ uint4 g_v[N_NODES_MAX * 8];
__device__ int   g_idx_is64;

#define MMA16816(c0, c1, c2, c3, a0, a1, a2, a3, b0, b1)                  \
    asm volatile(                                                          \
        "mma.sync.aligned.m16n8k16.row.col.f32.f16.f16.f32 "              \
        "{%0,%1,%2,%3}, {%4,%5,%6,%7}, {%8,%9}, {%0,%1,%2,%3};"           \
        : "+f"(c0), "+f"(c1), "+f"(c2), "+f"(c3)                           \
        : "r"(a0), "r"(a1), "r"(a2), "r"(a3), "r"(b0), "r"(b1))

__device__ __forceinline__ unsigned h2_as_u32(__half2 h) {
    return *(unsigned*)&h;
}

// ---------------------------------------------------------------------------
// Precompute via tensor cores. Split-precision on the Z side only:
//   acc = zh@wh + zl@wh  (wh = fp16(|w2|*W1); dropped z@wl ~ 2e-4 relative)
// PERSISTENT grid; each block preps weights once, grid-strides over tiles.
// z tile staged per-warp in smem via coalesced LDG.128; the same buffer is
// reused for the C-stage epilogue (coalesced 512B output runs).
// ---------------------------------------------------------------------------
__global__ __launch_bounds__(256)
void precompute_uv_kernel(const float* __restrict__ z,
                          const float* __restrict__ W1,
                          const float* __restrict__ b1,
                          const float* __restrict__ W2,
                          const int* __restrict__ ei_as_i32,
                          int n_nodes, int n_tiles) {
    extern __shared__ __align__(16) char smem_raw[];
    __half* whh   = (__half*)smem_raw;                   // [128][STRIDE_H]
    float*  b1c   = (float*)(whh + 128 * STRIDE_H);      // [128]
    float*  stage = b1c + 128;                           // 8 warps x 16 x ZST_STRIDE

    __shared__ int s_nz[4];
    const int tid = threadIdx.x;

    // dtype detection (block 0, warps 0-3 fully active)
    if (blockIdx.x == 0 && tid < 128) {
        int nz = (ei_as_i32[2 * tid + 1] != 0) ? 1 : 0;
        unsigned b = __ballot_sync(0xffffffffu, nz);
        if ((tid & 31) == 0) s_nz[tid >> 5] = (b != 0);
    }

    // Stage fp16 |w2|-scaled transposed weights (once per block).
    // W1 linear i = j*64+m: j<64 -> (n=m, k=j) u-part; j>=64 -> (n=64+m, k=j-64).
    for (int i = tid; i < 128 * HIDDEN; i += 256) {
        const int j = i >> 6, m = i & 63;
        const int n = (j < HIDDEN) ? m : (HIDDEN + m);
        const int k = (j < HIDDEN) ? j : (j - HIDDEN);
        whh[n * STRIDE_H + k] = __float2half_rn(W1[i] * fabsf(W2[m]));
    }
    if (tid < 128) {
        const int m = tid & (HIDDEN - 1);
        b1c[tid] = 0.5f * b1[m] * fabsf(W2[m]);
    }
    __syncthreads();

    if (blockIdx.x == 0 && tid == 0)
        g_idx_is64 = !(s_nz[0] | s_nz[1] | s_nz[2] | s_nz[3]);

    const int warp = tid >> 5, lane = tid & 31;
    const int g = lane >> 2, tig = lane & 3;
    float* zw = stage + warp * 16 * ZST_STRIDE;

    for (int tile = blockIdx.x; tile < n_tiles; tile += gridDim.x) {
        const long long wbase = (long long)tile * 128 + warp * 16;
        if (wbase >= n_nodes) continue;

        // Stage 16 z rows coalesced: 8x LDG.128 per lane pattern.
        #pragma unroll
        for (int it = 0; it < 8; it++) {
            const int idx = it * 32 + lane;        // float4 unit 0..255
            const int row = idx >> 4, ch = idx & 15;
            const long long gr = wbase + row;
            float4 val = make_float4(0.f, 0.f, 0.f, 0.f);
            if (gr < n_nodes) val = ((const float4*)z)[gr * 16 + ch];
            *(float4*)&zw[row * ZST_STRIDE + ch * 4] = val;
        }
        __syncwarp();

        float acc[16][4];
        #pragma unroll
        for (int t = 0; t < 16; t++) {
            const int c = t * 8 + tig * 2;
            acc[t][0] = b1c[c];  acc[t][1] = b1c[c + 1];
            acc[t][2] = b1c[c];  acc[t][3] = b1c[c + 1];
        }

        #pragma unroll
        for (int kt = 0; kt < 4; kt++) {
            const int k0 = kt * 16;
            const float2 f0 = *(const float2*)&zw[g * ZST_STRIDE + k0 + tig * 2];
            const float2 f1 = *(const float2*)&zw[(g + 8) * ZST_STRIDE + k0 + tig * 2];
            const float2 f2 = *(const float2*)&zw[g * ZST_STRIDE + k0 + 8 + tig * 2];
            const float2 f3 = *(const float2*)&zw[(g + 8) * ZST_STRIDE + k0 + 8 + tig * 2];

            __half2 h; float2 hf;
            unsigned ah[4], al[4];
            h = __floats2half2_rn(f0.x, f0.y); ah[0] = h2_as_u32(h);
            hf = __half22float2(h);
            al[0] = h2_as_u32(__floats2half2_rn(f0.x - hf.x, f0.y - hf.y));
            h = __floats2half2_rn(f1.x, f1.y); ah[1] = h2_as_u32(h);
            hf = __half22float2(h);
            al[1] = h2_as_u32(__floats2half2_rn(f1.x - hf.x, f1.y - hf.y));
            h = __floats2half2_rn(f2.x, f2.y); ah[2] = h2_as_u32(h);
            hf = __half22float2(h);
            al[2] = h2_as_u32(__floats2half2_rn(f2.x - hf.x, f2.y - hf.y));
            h = __floats2half2_rn(f3.x, f3.y); ah[3] = h2_as_u32(h);
            hf = __half22float2(h);
            al[3] = h2_as_u32(__floats2half2_rn(f3.x - hf.x, f3.y - hf.y));

            #pragma unroll
            for (int t = 0; t < 16; t++) {
                const int nb = t * 8 + g;
                const unsigned bh0 = *(const unsigned*)&whh[nb * STRIDE_H + k0 + tig * 2];
                const unsigned bh1 = *(const unsigned*)&whh[nb * STRIDE_H + k0 + 8 + tig * 2];
                MMA16816(acc[t][0], acc[t][1], acc[t][2], acc[t][3],
                         ah[0], ah[1], ah[2], ah[3], bh0, bh1);
                MMA16816(acc[t][0], acc[t][1], acc[t][2], acc[t][3],
                         al[0], al[1], al[2], al[3], bh0, bh1);
            }
        }
        __syncwarp();   // z reads done; reuse stage as C buffer

        // Epilogue: stage C (conflict-free STS), then coalesced 512B stores.
        __half2* cw = (__half2*)zw;
        #pragma unroll
        for (int t = 0; t < 16; t++) {
            cw[g * CST_STRIDE + t * 4 + tig]       = __floats2half2_rn(acc[t][0], acc[t][1]);
            cw[(g + 8) * CST_STRIDE + t * 4 + tig] = __floats2half2_rn(acc[t][2], acc[t][3]);
        }
        __syncwarp();

        #pragma unroll
        for (int q = 0; q < 4; q++) {
            const int nl = q * 4 + (lane >> 3);     // local node 0..15
            const int ch = lane & 7;                // uint4 chunk 0..7
            const long long gn = wbase + nl;
            if (gn < n_nodes) {
                g_u[gn * 8 + ch] = *(const uint4*)&cw[nl * CST_STRIDE + ch * 4];
                g_v[gn * 8 + ch] = *(const uint4*)&cw[nl * CST_STRIDE + 32 + ch * 4];
            }
        }
        __syncwarp();
    }
}

// ---------------------------------------------------------------------------
// One lane's 8-column signed-relu partial (b1,|W2| folded; sign = exact +-1).
// ---------------------------------------------------------------------------
__device__ __forceinline__ float oct_partial(uint4 u, uint4 v,
                                             const __half2* __restrict__ sg) {
    const __half2* up = (const __half2*)&u;
    const __half2* vp = (const __half2*)&v;
    const __half2 z2 = __float2half2_rn(0.f);
    __half2 acc2 = __hmul2(__hmax2(__hadd2(up[0], vp[0]), z2), sg[0]);
    acc2 = __hfma2(__hmax2(__hadd2(up[1], vp[1]), z2), sg[1], acc2);
    acc2 = __hfma2(__hmax2(__hadd2(up[2], vp[2]), z2), sg[2], acc2);
    acc2 = __hfma2(__hmax2(__hadd2(up[3], vp[3]), z2), sg[3], acc2);
    const float2 f = __half22float2(acc2);
    return f.x + f.y;
}

// ---------------------------------------------------------------------------
// Edge kernel (measured at its l1tex floor): 32 edges/warp; coalesced index
// load; 8 unrolled substeps of 4 edges; 8 lanes/edge gather one 16B chunk of
// u''[row], v''[col] via __ldcg.
// ---------------------------------------------------------------------------
template <bool FULL>
__device__ __forceinline__
void edge_tile(const long long base, int r_all, int c_all,
               const __half2* sg, float bias2, float* __restrict__ out,
               int n_edges, int oct, int j) {
    #pragma unroll
    for (int s = 0; s < 8; s++) {
        const int e_off = s * 4 + oct;
        const int r = __shfl_sync(0xffffffffu, r_all, e_off);
        const int c = __shfl_sync(0xffffffffu, c_all, e_off);

        const uint4 u = __ldcg(&g_u[(size_t)r * 8 + j]);
        const uint4 v = __ldcg(&g_v[(size_t)c * 8 + j]);

        float acc = oct_partial(u, v, sg);
        acc += __shfl_xor_sync(0xffffffffu, acc, 1);
        acc += __shfl_xor_sync(0xffffffffu, acc, 2);
        acc += __shfl_xor_sync(0xffffffffu, acc, 4);

        if (j == 0) {
            const long long e = base + e_off;
            if (FULL || e < n_edges) out[e] = acc + bias2;
        }
    }
}

__global__ __launch_bounds__(256)
void edge_decode_kernel(const void* __restrict__ ei_raw,
                        const float* __restrict__ W2,
                        const float* __restrict__ b2,
                        float* __restrict__ out,
                        int n_edges) {
    const int lane = threadIdx.x & 31;
    const int oct  = lane >> 3;
    const int j    = lane & 7;

    const long long base =
        (long long)((blockIdx.x * blockDim.x + threadIdx.x) >> 5) * 32;
    if (base >= n_edges) return;

    const int is64 = g_idx_is64;
    const long long* __restrict__ ei64 = (const long long*)ei_raw;
    const int*       __restrict__ ei32 = (const int*)ei_raw;

    const long long eL = base + lane;
    const bool haveL = eL < n_edges;
    int r_all, c_all;
    if (is64) {
        r_all = haveL ? (int)ei64[eL] : 0;
        c_all = haveL ? (int)ei64[(long long)n_edges + eL] : 0;
    } else {
        r_all = haveL ? ei32[eL] : 0;
        c_all = haveL ? ei32[(long long)n_edges + eL] : 0;
    }

    __half2 sg[4];
    #pragma unroll
    for (int i = 0; i < 4; i++)
        sg[i] = __floats2half2_rn(copysignf(1.f, W2[8 * j + 2 * i]),
                                  copysignf(1.f, W2[8 * j + 2 * i + 1]));
    const float bias2 = b2[0];

    if (base + 32 <= (long long)n_edges)
        edge_tile<true >(base, r_all, c_all, sg, bias2, out, n_edges, oct, j);
    else
        edge_tile<false>(base, r_all, c_all, sg, bias2, out, n_edges, oct, j);
}

// ---------------------------------------------------------------------------
// Launch. Inputs: z, edge_index [2,E], W1, b1, W2, b2. Output: f32 [E,1].
// ---------------------------------------------------------------------------
extern "C" void kernel_launch(void* const* d_in, const int* in_sizes, int n_in,
                              void* d_out, int out_size) {
    const float* z  = (const float*)d_in[0];
    const void*  ei = d_in[1];
    const float* W1 = (const float*)d_in[2];
    const float* b1 = (const float*)d_in[3];
    const float* W2 = (const float*)d_in[4];
    const float* b2 = (const float*)d_in[5];
    float* out = (float*)d_out;

    const int n_nodes = in_sizes[0] / HIDDEN;
    const int n_edges = in_sizes[1] / 2;

    // Phase 1: persistent tensor-core projections.
    {
        const int smem_bytes = 128 * STRIDE_H * 2          // whh
                             + 128 * 4                     // b1c
                             + 8 * 16 * ZST_STRIDE * 4;    // z/C stage
        cudaFuncSetAttribute(precompute_uv_kernel,
                             cudaFuncAttributeMaxDynamicSharedMemorySize,
                             smem_bytes);
        const int n_tiles = (n_nodes + 127) / 128;
        int blocks = 296;                                  // 2 per SM
        if (blocks > n_tiles) blocks = n_tiles;
        precompute_uv_kernel<<<blocks, 256, smem_bytes>>>(
            z, W1, b1, W2, (const int*)ei, n_nodes, n_tiles);
    }

    // Phase 2: edge decode (at its l1tex floor).
    {
        const int threads = 256;
        const int edges_per_block = 256;   // 8 warps x 32 edges
        const int blocks = (n_edges + edges_per_block - 1) / edges_per_block;
        edge_decode_kernel<<<blocks, threads>>>(ei, W2, b2, out, n_edges);
    }
}

// round 14
// speedup vs baseline: 1.3260x; 1.0032x over previous
#include <cuda_runtime.h>
#include <cuda_fp16.h>
#include <cuda_bf16.h>
#include <cstdint>

#define N_NODES_MAX 100000
#define HIDDEN 64
#define STRIDE_H 72     // weight smem stride (halves): conflict-free ldmatrix
#define ZH_STRIDE 72    // z-stage stride (halves)
#define CST_STRIDE 68   // C-stage stride (half2 units): conflict-free STS

// Per-node fp16 projections with |W2| and 0.5*b1 folded in:
//   u''_k = (z @ W1[0:64,:])_k   * |w2_k| + 0.5*b1_k*|w2_k|
//   v''_k = (z @ W1[64:128,:])_k * |w2_k| + 0.5*b1_k*|w2_k|
// Edge: out = sum_k sign(w2_k) * relu(u''_k + v''_k) + b2
__device__ uint4 g_u[N_NODES_MAX * 8];
__device__ uint4 g_v[N_NODES_MAX * 8];
__device__ int   g_idx_is64;

#define MMA16816(c0, c1, c2, c3, a0, a1, a2, a3, b0, b1)                  \
    asm volatile(                                                          \
        "mma.sync.aligned.m16n8k16.row.col.f32.f16.f16.f32 "              \
        "{%0,%1,%2,%3}, {%4,%5,%6,%7}, {%8,%9}, {%0,%1,%2,%3};"           \
        : "+f"(c0), "+f"(c1), "+f"(c2), "+f"(c3)                           \
        : "r"(a0), "r"(a1), "r"(a2), "r"(a3), "r"(b0), "r"(b1))

#define LDSM_X4(r0, r1, r2, r3, addr)                                      \
    asm volatile("ldmatrix.sync.aligned.m8n8.x4.shared.b16 "               \
                 "{%0,%1,%2,%3}, [%4];"                                    \
                 : "=r"(r0), "=r"(r1), "=r"(r2), "=r"(r3) : "r"(addr))

#define LDSM_X2(r0, r1, addr)                                              \
    asm volatile("ldmatrix.sync.aligned.m8n8.x2.shared.b16 "               \
                 "{%0,%1}, [%2];"                                          \
                 : "=r"(r0), "=r"(r1) : "r"(addr))

__device__ __forceinline__ unsigned smem_u32(const void* p) {
    return (unsigned)__cvta_generic_to_shared(p);
}

// ---------------------------------------------------------------------------
// Precompute via tensor cores; split-precision on Z (zh+zl fp16), W fp16:
//   acc = zh@wh + zl@wh
// PERSISTENT grid; per-block weight prep; z software-pipelined (next tile's
// LDG issued before the MMA loop); A/B fragments via ldmatrix; C staged in
// smem (overlaying the z-stage) and stored as coalesced 512B runs.
// ---------------------------------------------------------------------------
__global__ __launch_bounds__(256, 2)
void precompute_uv_kernel(const float* __restrict__ z,
                          const float* __restrict__ W1,
                          const float* __restrict__ b1,
                          const float* __restrict__ W2,
                          const int* __restrict__ ei_as_i32,
                          int n_nodes, int n_tiles) {
    extern __shared__ __align__(16) char smem_raw[];
    __half* whh   = (__half*)smem_raw;                   // [128][STRIDE_H]
    float*  b1c   = (float*)(whh + 128 * STRIDE_H);      // [128]
    __half* zst   = (__half*)(b1c + 128);                // 8 x (zh[16][72] + zl[16][72])

    __shared__ int s_nz[4];
    const int tid = threadIdx.x;

    // dtype detection (block 0, warps 0-3 fully active)
    if (blockIdx.x == 0 && tid < 128) {
        int nz = (ei_as_i32[2 * tid + 1] != 0) ? 1 : 0;
        unsigned b = __ballot_sync(0xffffffffu, nz);
        if ((tid & 31) == 0) s_nz[tid >> 5] = (b != 0);
    }

    // Stage fp16 |w2|-scaled transposed weights (once per block).
    // W1 linear i = j*64+m: j<64 -> (n=m, k=j) u-part; j>=64 -> (n=64+m, k=j-64).
    for (int i = tid; i < 128 * HIDDEN; i += 256) {
        const int j = i >> 6, m = i & 63;
        const int n = (j < HIDDEN) ? m : (HIDDEN + m);
        const int k = (j < HIDDEN) ? j : (j - HIDDEN);
        whh[n * STRIDE_H + k] = __float2half_rn(W1[i] * fabsf(W2[m]));
    }
    if (tid < 128) {
        const int m = tid & (HIDDEN - 1);
        b1c[tid] = 0.5f * b1[m] * fabsf(W2[m]);
    }
    __syncthreads();

    if (blockIdx.x == 0 && tid == 0)
        g_idx_is64 = !(s_nz[0] | s_nz[1] | s_nz[2] | s_nz[3]);

    const int warp = tid >> 5, lane = tid & 31;
    const int g = lane >> 2, tig = lane & 3;

    __half* zh = zst + warp * (2 * 16 * ZH_STRIDE);
    __half* zl = zh + 16 * ZH_STRIDE;

    // ldmatrix shared addresses (lane-dependent, k0 added per kt).
    // A (x4): rows 0-15 from lanes 0-15, +8-col tile from lanes 16-31.
    const unsigned zh_s = smem_u32(zh);
    const unsigned zl_s = smem_u32(zl);
    const unsigned aoff = (unsigned)(((lane & 15) * ZH_STRIDE + ((lane >> 4) << 3)) * 2);
    // B (x2): 8 rows (output cols) from lanes 0-7, +8-k tile from lanes 8-15.
    const unsigned wh_s = smem_u32(whh);
    const unsigned boff = (unsigned)((((lane & 15) & 7) * STRIDE_H + (((lane & 15) & 8) ? 8 : 0)) * 2);

    // z row load (coalesced): lane pattern idx = it*32+lane -> (row, chunk)
    auto load_zf = [&](long long tile_base, float4* zf) {
        #pragma unroll
        for (int it = 0; it < 8; it++) {
            const int idx = it * 32 + lane;
            const int row = idx >> 4, ch = idx & 15;
            const long long gr = tile_base + row;
            zf[it] = make_float4(0.f, 0.f, 0.f, 0.f);
            if (gr < n_nodes) zf[it] = ((const float4*)z)[gr * 16 + ch];
        }
    };

    int tile = blockIdx.x;
    if (tile >= n_tiles) return;

    float4 zf[8];
    load_zf((long long)tile * 128 + warp * 16, zf);

    while (tile < n_tiles) {
        const long long wbase = (long long)tile * 128 + warp * 16;

        // Stage zh/zl from registers (converted once per tile).
        #pragma unroll
        for (int it = 0; it < 8; it++) {
            const int idx = it * 32 + lane;
            const int row = idx >> 4, ch = idx & 15;
            const float4 v = zf[it];
            const __half2 h0 = __floats2half2_rn(v.x, v.y);
            const __half2 h1 = __floats2half2_rn(v.z, v.w);
            const float2 r0 = __half22float2(h0);
            const float2 r1 = __half22float2(h1);
            const __half2 l0 = __floats2half2_rn(v.x - r0.x, v.y - r0.y);
            const __half2 l1 = __floats2half2_rn(v.z - r1.x, v.w - r1.y);
            uint2 ph, pl;
            ph.x = *(const unsigned*)&h0;  ph.y = *(const unsigned*)&h1;
            pl.x = *(const unsigned*)&l0;  pl.y = *(const unsigned*)&l1;
            *(uint2*)&zh[row * ZH_STRIDE + ch * 4] = ph;
            *(uint2*)&zl[row * ZH_STRIDE + ch * 4] = pl;
        }
        __syncwarp();

        // Prefetch next tile's z (latency hidden behind the MMA loop).
        const int next = tile + gridDim.x;
        if (next < n_tiles)
            load_zf((long long)next * 128 + warp * 16, zf);

        float acc[16][4];
        #pragma unroll
        for (int t = 0; t < 16; t++) {
            const int c = t * 8 + tig * 2;
            acc[t][0] = b1c[c];  acc[t][1] = b1c[c + 1];
            acc[t][2] = b1c[c];  acc[t][3] = b1c[c + 1];
        }

        #pragma unroll
        for (int kt = 0; kt < 4; kt++) {
            const unsigned k0b = (unsigned)(kt * 16 * 2);
            unsigned ah0, ah1, ah2, ah3, al0, al1, al2, al3;
            LDSM_X4(ah0, ah1, ah2, ah3, zh_s + aoff + k0b);
            LDSM_X4(al0, al1, al2, al3, zl_s + aoff + k0b);

            unsigned baddr = wh_s + boff + k0b;
            #pragma unroll
            for (int t = 0; t < 16; t++) {
                unsigned b0, b1r;
                LDSM_X2(b0, b1r, baddr);
                baddr += 8 * STRIDE_H * 2;   // next 8 output cols
                MMA16816(acc[t][0], acc[t][1], acc[t][2], acc[t][3],
                         ah0, ah1, ah2, ah3, b0, b1r);
                MMA16816(acc[t][0], acc[t][1], acc[t][2], acc[t][3],
                         al0, al1, al2, al3, b0, b1r);
            }
        }
        __syncwarp();   // z-stage reads done; overlay C on zh/zl region

        // Epilogue: stage C (conflict-free STS), then coalesced 512B stores.
        __half2* cw = (__half2*)zh;
        #pragma unroll
        for (int t = 0; t < 16; t++) {
            cw[g * CST_STRIDE + t * 4 + tig]       = __floats2half2_rn(acc[t][0], acc[t][1]);
            cw[(g + 8) * CST_STRIDE + t * 4 + tig] = __floats2half2_rn(acc[t][2], acc[t][3]);
        }
        __syncwarp();

        #pragma unroll
        for (int q = 0; q < 4; q++) {
            const int nl = q * 4 + (lane >> 3);     // local node 0..15
            const int ch = lane & 7;                // uint4 chunk 0..7
            const long long gn = wbase + nl;
            if (gn < n_nodes) {
                g_u[gn * 8 + ch] = *(const uint4*)&cw[nl * CST_STRIDE + ch * 4];
                g_v[gn * 8 + ch] = *(const uint4*)&cw[nl * CST_STRIDE + 32 + ch * 4];
            }
        }
        __syncwarp();

        tile = next;
    }
}

// ---------------------------------------------------------------------------
// One lane's 8-column signed-relu partial (b1,|W2| folded; sign = exact +-1).
// ---------------------------------------------------------------------------
__device__ __forceinline__ float oct_partial(uint4 u, uint4 v,
                                             const __half2* __restrict__ sg) {
    const __half2* up = (const __half2*)&u;
    const __half2* vp = (const __half2*)&v;
    const __half2 z2 = __float2half2_rn(0.f);
    __half2 acc2 = __hmul2(__hmax2(__hadd2(up[0], vp[0]), z2), sg[0]);
    acc2 = __hfma2(__hmax2(__hadd2(up[1], vp[1]), z2), sg[1], acc2);
    acc2 = __hfma2(__hmax2(__hadd2(up[2], vp[2]), z2), sg[2], acc2);
    acc2 = __hfma2(__hmax2(__hadd2(up[3], vp[3]), z2), sg[3], acc2);
    const float2 f = __half22float2(acc2);
    return f.x + f.y;
}

// ---------------------------------------------------------------------------
// Edge kernel (at its l1tex sector floor): 32 edges/warp; coalesced index
// load; 8 unrolled substeps of 4 edges; 8 lanes/edge gather one 16B chunk of
// u''[row], v''[col] via __ldcg.
// ---------------------------------------------------------------------------
template <bool FULL>
__device__ __forceinline__
void edge_tile(const long long base, int r_all, int c_all,
               const __half2* sg, float bias2, float* __restrict__ out,
               int n_edges, int oct, int j) {
    #pragma unroll
    for (int s = 0; s < 8; s++) {
        const int e_off = s * 4 + oct;
        const int r = __shfl_sync(0xffffffffu, r_all, e_off);
        const int c = __shfl_sync(0xffffffffu, c_all, e_off);

        const uint4 u = __ldcg(&g_u[(size_t)r * 8 + j]);
        const uint4 v = __ldcg(&g_v[(size_t)c * 8 + j]);

        float acc = oct_partial(u, v, sg);
        acc += __shfl_xor_sync(0xffffffffu, acc, 1);
        acc += __shfl_xor_sync(0xffffffffu, acc, 2);
        acc += __shfl_xor_sync(0xffffffffu, acc, 4);

        if (j == 0) {
            const long long e = base + e_off;
            if (FULL || e < n_edges) out[e] = acc + bias2;
        }
    }
}

__global__ __launch_bounds__(256)
void edge_decode_kernel(const void* __restrict__ ei_raw,
                        const float* __restrict__ W2,
                        const float* __restrict__ b2,
                        float* __restrict__ out,
                        int n_edges) {
    const int lane = threadIdx.x & 31;
    const int oct  = lane >> 3;
    const int j    = lane & 7;

    const long long base =
        (long long)((blockIdx.x * blockDim.x + threadIdx.x) >> 5) * 32;
    if (base >= n_edges) return;

    const int is64 = g_idx_is64;
    const long long* __restrict__ ei64 = (const long long*)ei_raw;
    const int*       __restrict__ ei32 = (const int*)ei_raw;

    const long long eL = base + lane;
    const bool haveL = eL < n_edges;
    int r_all, c_all;
    if (is64) {
        r_all = haveL ? (int)ei64[eL] : 0;
        c_all = haveL ? (int)ei64[(long long)n_edges + eL] : 0;
    } else {
        r_all = haveL ? ei32[eL] : 0;
        c_all = haveL ? ei32[(long long)n_edges + eL] : 0;
    }

    __half2 sg[4];
    #pragma unroll
    for (int i = 0; i < 4; i++)
        sg[i] = __floats2half2_rn(copysignf(1.f, W2[8 * j + 2 * i]),
                                  copysignf(1.f, W2[8 * j + 2 * i + 1]));
    const float bias2 = b2[0];

    if (base + 32 <= (long long)n_edges)
        edge_tile<true >(base, r_all, c_all, sg, bias2, out, n_edges, oct, j);
    else
        edge_tile<false>(base, r_all, c_all, sg, bias2, out, n_edges, oct, j);
}

// ---------------------------------------------------------------------------
// Launch. Inputs: z, edge_index [2,E], W1, b1, W2, b2. Output: f32 [E,1].
// ---------------------------------------------------------------------------
extern "C" void kernel_launch(void* const* d_in, const int* in_sizes, int n_in,
                              void* d_out, int out_size) {
    const float* z  = (const float*)d_in[0];
    const void*  ei = d_in[1];
    const float* W1 = (const float*)d_in[2];
    const float* b1 = (const float*)d_in[3];
    const float* W2 = (const float*)d_in[4];
    const float* b2 = (const float*)d_in[5];
    float* out = (float*)d_out;

    const int n_nodes = in_sizes[0] / HIDDEN;
    const int n_edges = in_sizes[1] / 2;

    // Phase 1: persistent tensor-core projections (ldmatrix + z pipelining).
    {
        const int smem_bytes = 128 * STRIDE_H * 2          // whh
                             + 128 * 4                     // b1c
                             + 8 * 2 * 16 * ZH_STRIDE * 2; // zh+zl stage (C overlays)
        cudaFuncSetAttribute(precompute_uv_kernel,
                             cudaFuncAttributeMaxDynamicSharedMemorySize,
                             smem_bytes);
        const int n_tiles = (n_nodes + 127) / 128;
        int blocks = 296;                                  // 2 per SM
        if (blocks > n_tiles) blocks = n_tiles;
        precompute_uv_kernel<<<blocks, 256, smem_bytes>>>(
            z, W1, b1, W2, (const int*)ei, n_nodes, n_tiles);
    }

    // Phase 2: edge decode (at its l1tex floor).
    {
        const int threads = 256;
        const int edges_per_block = 256;   // 8 warps x 32 edges
        const int blocks = (n_edges + edges_per_block - 1) / edges_per_block;
        edge_decode_kernel<<<blocks, threads>>>(ei, W2, b2, out, n_edges);
    }
}